// round 3
// baseline (speedup 1.0000x reference)
#include <cuda_runtime.h>
#include <cuda_bf16.h>
#include <math.h>

// Problem dims
#define Bb 16
#define Uu 48
#define Ww 96
#define Vv 30000
#define Dd 256
#define Hh 512
#define G3 (3*Hh)   // 1536
#define BU (Bb*Uu)  // 768
#define SOUT (Bb*Uu*Hh) // 393216

// -------------------- device scratch (no allocs allowed) --------------------
__device__ float g_table[(size_t)Vv*G3];     // emb @ w_ih_w^T + b_ih_w : 184 MB
__device__ float g_gh[BU*G3];                // word-step gh scratch
__device__ float g_wh[2][BU*Hh];             // word hidden ping-pong
__device__ float g_utt_in[BU*Hh];            // gathered word outputs (B,U,H)
__device__ float g_gi_u[BU*G3];
__device__ float g_utt_h[2][Bb*Hh];
__device__ float g_utt_hnew[Bb*Hh];
__device__ float g_utt_ys[BU*Hh];
__device__ int   g_bnd[BU];
__device__ float g_seg_in[BU*Hh];
__device__ float g_gi_s[BU*G3];
__device__ float g_seg_h[2][Bb*Hh];
__device__ int   g_slen[Bb];

__device__ __forceinline__ float sigmoidf(float x) { return 1.0f / (1.0f + expf(-x)); }

// -------------------- generic NT GEMM: C[M,N] = A[M,K] * W[N,K]^T + bias[N] ----
// 64x64 tile, TK=16, 256 threads, 4x4 microtile. N % 64 == 0, K % 16 == 0 assumed.
#define TM 64
#define TN 64
#define TK 16
__global__ void gemm_nt(const float* __restrict__ A, const float* __restrict__ W,
                        const float* __restrict__ bias, float* __restrict__ C,
                        int M, int N, int K) {
    __shared__ float As[TK][TM + 1];
    __shared__ float Ws[TK][TN + 1];
    const int bm = blockIdx.x * TM;
    const int bn = blockIdx.y * TN;
    const int tid = threadIdx.x;
    const int tx = tid & 15;
    const int ty = tid >> 4;
    float acc[4][4] = {};
    for (int k0 = 0; k0 < K; k0 += TK) {
        #pragma unroll
        for (int i = tid; i < TM * TK; i += 256) {
            int r = i / TK, c = i % TK;
            int gm = bm + r;
            As[c][r] = (gm < M) ? A[(size_t)gm * K + k0 + c] : 0.0f;
        }
        #pragma unroll
        for (int i = tid; i < TN * TK; i += 256) {
            int r = i / TK, c = i % TK;
            Ws[c][r] = W[(size_t)(bn + r) * K + k0 + c];
        }
        __syncthreads();
        #pragma unroll
        for (int kk = 0; kk < TK; kk++) {
            float a[4], b[4];
            #pragma unroll
            for (int i = 0; i < 4; i++) a[i] = As[kk][ty * 4 + i];
            #pragma unroll
            for (int j = 0; j < 4; j++) b[j] = Ws[kk][tx * 4 + j];
            #pragma unroll
            for (int i = 0; i < 4; i++)
                #pragma unroll
                for (int j = 0; j < 4; j++)
                    acc[i][j] = fmaf(a[i], b[j], acc[i][j]);
        }
        __syncthreads();
    }
    #pragma unroll
    for (int i = 0; i < 4; i++) {
        int gm = bm + ty * 4 + i;
        if (gm >= M) continue;
        #pragma unroll
        for (int j = 0; j < 4; j++) {
            int gn = bn + tx * 4 + j;
            C[(size_t)gm * N + gn] = acc[i][j] + bias[gn];
        }
    }
}

// -------------------- init kernels --------------------
__global__ void zero_f(float* p, int n) {
    int i = blockIdx.x * blockDim.x + threadIdx.x;
    if (i < n) p[i] = 0.0f;
}
__global__ void bcast_h0(const float* __restrict__ h0, float* __restrict__ h) {
    int i = blockIdx.x * blockDim.x + threadIdx.x; // Bb*Hh
    h[i] = h0[i & (Hh - 1)];
}

// -------------------- word GRU gate (fused with gi gather + length gather) ----
__global__ void word_gate(const int* __restrict__ tokens, const int* __restrict__ wlen,
                          const float* __restrict__ gh, const float* __restrict__ hprev,
                          float* __restrict__ hnext, float* __restrict__ utt_in, int t) {
    int idx = blockIdx.x * blockDim.x + threadIdx.x; // BU*Hh
    int i = idx >> 9;       // sequence (b*U+u)
    int c = idx & (Hh - 1); // hidden index
    int tok = __ldg(&tokens[i * Ww + t]);
    const float* gi  = g_table + (size_t)tok * G3;
    const float* ghr = gh + (size_t)i * G3;
    float r = sigmoidf(gi[c]        + ghr[c]);
    float z = sigmoidf(gi[c + Hh]   + ghr[c + Hh]);
    float n = tanhf   (gi[c + 2*Hh] + r * ghr[c + 2*Hh]);
    float h  = hprev[idx];
    float hn = (1.0f - z) * n + z * h;
    hnext[idx] = hn;
    if (t == __ldg(&wlen[i]) - 1) utt_in[idx] = hn;
}

// -------------------- small (batch=16) GRU step: warp per hidden column -------
// Computes h_new for all (b,c); writes hnew buffer and optionally ys[(b*U+u)].
__global__ void small_step(const float* __restrict__ gi, const float* __restrict__ whh,
                           const float* __restrict__ bhh, const float* __restrict__ hprev,
                           float* __restrict__ hnew, float* __restrict__ ys, int u) {
    int w = (blockIdx.x * blockDim.x + threadIdx.x) >> 5; // global warp id: Bb*Hh warps
    int lane = threadIdx.x & 31;
    int b = w >> 9;
    int c = w & (Hh - 1);
    const float* h  = hprev + b * Hh;
    const float* w0 = whh + (size_t)c * Hh;
    const float* w1 = whh + (size_t)(c + Hh) * Hh;
    const float* w2 = whh + (size_t)(c + 2*Hh) * Hh;
    float s0 = 0.f, s1 = 0.f, s2 = 0.f;
    #pragma unroll 4
    for (int k = lane; k < Hh; k += 32) {
        float hv = h[k];
        s0 = fmaf(hv, w0[k], s0);
        s1 = fmaf(hv, w1[k], s1);
        s2 = fmaf(hv, w2[k], s2);
    }
    #pragma unroll
    for (int o = 16; o; o >>= 1) {
        s0 += __shfl_down_sync(0xffffffffu, s0, o);
        s1 += __shfl_down_sync(0xffffffffu, s1, o);
        s2 += __shfl_down_sync(0xffffffffu, s2, o);
    }
    if (lane == 0) {
        const float* gir = gi + (size_t)(b * Uu + u) * G3;
        float r = sigmoidf(gir[c]        + s0 + bhh[c]);
        float z = sigmoidf(gir[c + Hh]   + s1 + bhh[c + Hh]);
        float n = tanhf   (gir[c + 2*Hh] + r * (s2 + bhh[c + 2*Hh]));
        float hn = (1.0f - z) * n + z * h[c];
        hnew[b * Hh + c] = hn;
        if (ys) ys[(size_t)(b * Uu + u) * Hh + c] = hn;
    }
}

// -------------------- adaptive gate: sigmoid(h_new @ w_g + b_g) > 0.5 --------
__global__ void utt_gate(const float* __restrict__ hnew, const float* __restrict__ wg,
                         const float* __restrict__ bg, const float* __restrict__ h0,
                         float* __restrict__ hnext, int u) {
    int b = blockIdx.x;      // 16 blocks
    int c = threadIdx.x;     // 512 threads
    __shared__ float red[Hh];
    __shared__ int sb;
    float hn = hnew[b * Hh + c];
    red[c] = hn * wg[c];
    __syncthreads();
    #pragma unroll
    for (int s = Hh / 2; s > 0; s >>= 1) {
        if (c < s) red[c] += red[c + s];
        __syncthreads();
    }
    if (c == 0) {
        float g = sigmoidf(red[0] + bg[0]);
        sb = (g > 0.5f) ? 1 : 0;
        g_bnd[b * Uu + u] = sb;
    }
    __syncthreads();
    hnext[b * Hh + c] = sb ? h0[c] : hn;
}

// -------------------- mask / cumsum / compaction scatter ----------------------
__global__ void mask_scatter(const int* __restrict__ ulen) {
    int b = blockIdx.x;   // 16 blocks
    int c = threadIdx.x;  // 512 threads
    for (int u = 0; u < Uu; u++)
        g_seg_in[(size_t)(b * Uu + u) * Hh + c] = 0.0f;
    int ul = ulen[b];
    int cnt = 0;
    for (int u = 0; u < Uu; u++) {
        bool m = (u < ul) && (g_bnd[b * Uu + u] || (u == ul - 1));
        if (m) {
            g_seg_in[(size_t)(b * Uu + cnt) * Hh + c] =
                g_utt_ys[(size_t)(b * Uu + u) * Hh + c];
            cnt++;
        }
    }
    if (c == 0) g_slen[b] = cnt;
}

__global__ void write_slen(float* out, int out_size) {
    int b = threadIdx.x; // 16 threads
    if (b < Bb && SOUT + b < out_size) out[SOUT + b] = (float)g_slen[b];
}

// -------------------- host-side orchestration --------------------
extern "C" void kernel_launch(void* const* d_in, const int* in_sizes, int n_in,
                              void* d_out, int out_size) {
    const int*   input  = (const int*)  d_in[0];
    const int*   u_len  = (const int*)  d_in[1];
    const int*   w_len  = (const int*)  d_in[2];
    const float* emb    = (const float*)d_in[3];
    const float* w_ih_w = (const float*)d_in[4];
    const float* w_hh_w = (const float*)d_in[5];
    const float* b_ih_w = (const float*)d_in[6];
    const float* b_hh_w = (const float*)d_in[7];
    const float* w_ih_u = (const float*)d_in[8];
    const float* w_hh_u = (const float*)d_in[9];
    const float* b_ih_u = (const float*)d_in[10];
    const float* b_hh_u = (const float*)d_in[11];
    const float* w_g    = (const float*)d_in[12];
    const float* b_g    = (const float*)d_in[13];
    const float* w_ih_s = (const float*)d_in[14];
    const float* w_hh_s = (const float*)d_in[15];
    const float* b_ih_s = (const float*)d_in[16];
    const float* b_hh_s = (const float*)d_in[17];
    const float* h0     = (const float*)d_in[18];
    float* out = (float*)d_out;

    // Resolve device-symbol addresses fresh every call (no static caching —
    // harness forbids static guards). Host API only; capture-safe.
    void* tmp;
    float *p_table, *p_gh, *p_wh0, *p_wh1, *p_utt_in, *p_gi_u;
    float *p_utt_h0, *p_utt_h1, *p_utt_hnew, *p_utt_ys, *p_gi_s;
    float *p_seg_in, *p_seg_h0, *p_seg_h1;
    cudaGetSymbolAddress(&tmp, g_table);   p_table = (float*)tmp;
    cudaGetSymbolAddress(&tmp, g_gh);      p_gh = (float*)tmp;
    cudaGetSymbolAddress(&tmp, g_wh);      p_wh0 = (float*)tmp; p_wh1 = p_wh0 + BU*Hh;
    cudaGetSymbolAddress(&tmp, g_utt_in);  p_utt_in = (float*)tmp;
    cudaGetSymbolAddress(&tmp, g_gi_u);    p_gi_u = (float*)tmp;
    cudaGetSymbolAddress(&tmp, g_utt_h);   p_utt_h0 = (float*)tmp; p_utt_h1 = p_utt_h0 + Bb*Hh;
    cudaGetSymbolAddress(&tmp, g_utt_hnew);p_utt_hnew = (float*)tmp;
    cudaGetSymbolAddress(&tmp, g_utt_ys);  p_utt_ys = (float*)tmp;
    cudaGetSymbolAddress(&tmp, g_gi_s);    p_gi_s = (float*)tmp;
    cudaGetSymbolAddress(&tmp, g_seg_in);  p_seg_in = (float*)tmp;
    cudaGetSymbolAddress(&tmp, g_seg_h);   p_seg_h0 = (float*)tmp; p_seg_h1 = p_seg_h0 + Bb*Hh;

    // 1) Vocab-projected input table: table = emb @ w_ih_w^T + b_ih_w  (30000x1536, K=256)
    {
        dim3 grid((Vv + TM - 1) / TM, G3 / TN);
        gemm_nt<<<grid, 256>>>(emb, w_ih_w, b_ih_w, p_table, Vv, G3, Dd);
    }

    // 2) Word-level GRU: 96 sequential steps over 768 sequences
    zero_f<<<(BU * Hh + 255) / 256, 256>>>(p_wh0, BU * Hh);
    {
        float* hp[2] = {p_wh0, p_wh1};
        int cur = 0;
        dim3 ggrid((BU + TM - 1) / TM, G3 / TN);  // (12, 24)
        for (int t = 0; t < Ww; t++) {
            gemm_nt<<<ggrid, 256>>>(hp[cur], w_hh_w, b_hh_w, p_gh, BU, G3, Hh);
            word_gate<<<(BU * Hh) / 256, 256>>>(input, w_len, p_gh, hp[cur],
                                                hp[1 - cur], p_utt_in, t);
            cur ^= 1;
        }
    }

    // 3) Utterance-level adaptive GRU
    {
        dim3 ggrid((BU + TM - 1) / TM, G3 / TN);
        gemm_nt<<<ggrid, 256>>>(p_utt_in, w_ih_u, b_ih_u, p_gi_u, BU, G3, Hh);
    }
    bcast_h0<<<(Bb * Hh + 255) / 256, 256>>>(h0, p_utt_h0);
    {
        float* hp[2] = {p_utt_h0, p_utt_h1};
        int cur = 0;
        int blocks = Bb * Hh * 32 / 256;     // 1024 blocks of 8 warps
        for (int u = 0; u < Uu; u++) {
            small_step<<<blocks, 256>>>(p_gi_u, w_hh_u, b_hh_u, hp[cur],
                                        p_utt_hnew, p_utt_ys, u);
            utt_gate<<<Bb, Hh>>>(p_utt_hnew, w_g, b_g, h0, hp[1 - cur], u);
            cur ^= 1;
        }
    }

    // 4) Boundary mask + compaction into segment inputs
    mask_scatter<<<Bb, Hh>>>(u_len);

    // 5) Segment-level GRU -> writes s_output directly into d_out
    {
        dim3 ggrid((BU + TM - 1) / TM, G3 / TN);
        gemm_nt<<<ggrid, 256>>>(p_seg_in, w_ih_s, b_ih_s, p_gi_s, BU, G3, Hh);
    }
    zero_f<<<(Bb * Hh + 255) / 256, 256>>>(p_seg_h0, Bb * Hh);
    {
        float* hp[2] = {p_seg_h0, p_seg_h1};
        int cur = 0;
        int blocks = Bb * Hh * 32 / 256;
        for (int u = 0; u < Uu; u++) {
            small_step<<<blocks, 256>>>(p_gi_s, w_hh_s, b_hh_s, hp[cur],
                                        hp[1 - cur], out, u);
            cur ^= 1;
        }
    }

    // 6) s_len tail (as float), guarded by out_size
    write_slen<<<1, 32>>>(out, out_size);
}

// round 4
// speedup vs baseline: 1.1744x; 1.1744x over previous
#include <cuda_runtime.h>
#include <cuda_bf16.h>
#include <math.h>

// Problem dims
#define Bb 16
#define Uu 48
#define Ww 96
#define Vv 30000
#define Dd 256
#define Hh 512
#define G3 (3*Hh)   // 1536
#define BU (Bb*Uu)  // 768
#define SOUT (Bb*Uu*Hh) // 393216

// -------------------- device scratch (no allocs allowed) --------------------
__device__ float g_table[(size_t)Vv*G3];     // emb @ w_ih_w^T + b_ih_w : 184 MB
__device__ float g_wh[2][BU*Hh];             // word hidden ping-pong
__device__ float g_utt_in[BU*Hh];            // gathered word outputs (B,U,H)
__device__ float g_gi_u[BU*G3];
__device__ float g_utt_h[2][Bb*Hh];
__device__ float g_utt_hnew[Bb*Hh];
__device__ float g_utt_ys[BU*Hh];
__device__ int   g_bnd[BU];
__device__ float g_seg_in[BU*Hh];
__device__ float g_gi_s[BU*G3];
__device__ float g_seg_h[2][Bb*Hh];
__device__ int   g_slen[Bb];

__device__ __forceinline__ float sigmoidf(float x) { return 1.0f / (1.0f + expf(-x)); }

// -------------------- generic NT GEMM: C[M,N] = A[M,K] * W[N,K]^T + bias[N] ----
// 64x64 tile, TK=16, 256 threads, 4x4 microtile, float4 global loads.
// N % 64 == 0, K % 16 == 0 assumed. M arbitrary (row-guarded).
#define TM 64
#define TN 64
#define TK 16
__global__ void gemm_nt(const float* __restrict__ A, const float* __restrict__ W,
                        const float* __restrict__ bias, float* __restrict__ C,
                        int M, int N, int K) {
    __shared__ float As[TK][TM + 1];
    __shared__ float Ws[TK][TN + 1];
    const int bm = blockIdx.x * TM;
    const int bn = blockIdx.y * TN;
    const int tid = threadIdx.x;
    const int tx = tid & 15;
    const int ty = tid >> 4;
    const int lr = tid >> 2;          // 0..63 row within tile
    const int lk = (tid & 3) * 4;     // k quad
    float acc[4][4] = {};
    for (int k0 = 0; k0 < K; k0 += TK) {
        // A tile: 64 rows x 16 k = 256 float4, one per thread
        {
            int gm = bm + lr;
            float4 v = make_float4(0.f, 0.f, 0.f, 0.f);
            if (gm < M) v = *(const float4*)&A[(size_t)gm * K + k0 + lk];
            As[lk + 0][lr] = v.x; As[lk + 1][lr] = v.y;
            As[lk + 2][lr] = v.z; As[lk + 3][lr] = v.w;
        }
        // W tile
        {
            float4 v = *(const float4*)&W[(size_t)(bn + lr) * K + k0 + lk];
            Ws[lk + 0][lr] = v.x; Ws[lk + 1][lr] = v.y;
            Ws[lk + 2][lr] = v.z; Ws[lk + 3][lr] = v.w;
        }
        __syncthreads();
        #pragma unroll
        for (int kk = 0; kk < TK; kk++) {
            float a[4], b[4];
            #pragma unroll
            for (int i = 0; i < 4; i++) a[i] = As[kk][ty * 4 + i];
            #pragma unroll
            for (int j = 0; j < 4; j++) b[j] = Ws[kk][tx * 4 + j];
            #pragma unroll
            for (int i = 0; i < 4; i++)
                #pragma unroll
                for (int j = 0; j < 4; j++)
                    acc[i][j] = fmaf(a[i], b[j], acc[i][j]);
        }
        __syncthreads();
    }
    #pragma unroll
    for (int i = 0; i < 4; i++) {
        int gm = bm + ty * 4 + i;
        if (gm >= M) continue;
        #pragma unroll
        for (int j = 0; j < 4; j++) {
            int gn = bn + tx * 4 + j;
            C[(size_t)gm * N + gn] = acc[i][j] + bias[gn];
        }
    }
}

// -------------------- fused word GRU step ------------------------------------
// One kernel per timestep: computes gh = h @ w_hh^T (3 gates), applies GRU
// nonlinearity with gi gathered from the vocab table, writes h_next and
// (at t == wlen-1) utt_in. Tile: 32 rows x 64 c, 3 gate accumulators.
#define WTM 32
#define WTN 64
#define WTK 16
#define WNIT (Hh / WTK)   // 32 k-iterations

__global__ void __launch_bounds__(256) word_step(
    const float* __restrict__ hprev, const float* __restrict__ whh,
    const float* __restrict__ bhh, const int* __restrict__ tokens,
    const int* __restrict__ wlen, float* __restrict__ hnext,
    float* __restrict__ utt_in, int t)
{
    __shared__ float As[2][WTK][WTM + 4];
    __shared__ float Ws[2][3][WTK][WTN + 4];

    const int bm = blockIdx.x * WTM;   // 24 blocks over rows
    const int bn = blockIdx.y * WTN;   // 8 blocks over c
    const int tid = threadIdx.x;
    const int tx = tid & 15;           // c microtile: columns tx*4..tx*4+3
    const int ty = tid >> 4;           // row microtile: rows ty*2, ty*2+1
    const int lr = tid >> 2;           // loader row 0..63
    const int lk = (tid & 3) * 4;      // loader k quad

    float accr[2][4] = {}, accz[2][4] = {}, accn[2][4] = {};

    // prefetch registers
    float4 pa = make_float4(0.f, 0.f, 0.f, 0.f);
    float4 pw0, pw1, pw2;

    // ---- prologue: load k0 = 0 into buf 0 ----
    if (tid < 128) {
        pa = *(const float4*)&hprev[(size_t)(bm + lr) * Hh + lk];
        As[0][lk + 0][lr] = pa.x; As[0][lk + 1][lr] = pa.y;
        As[0][lk + 2][lr] = pa.z; As[0][lk + 3][lr] = pa.w;
    }
    {
        pw0 = *(const float4*)&whh[(size_t)(bn + lr) * Hh + lk];
        pw1 = *(const float4*)&whh[(size_t)(bn + Hh + lr) * Hh + lk];
        pw2 = *(const float4*)&whh[(size_t)(bn + 2 * Hh + lr) * Hh + lk];
        Ws[0][0][lk + 0][lr] = pw0.x; Ws[0][0][lk + 1][lr] = pw0.y;
        Ws[0][0][lk + 2][lr] = pw0.z; Ws[0][0][lk + 3][lr] = pw0.w;
        Ws[0][1][lk + 0][lr] = pw1.x; Ws[0][1][lk + 1][lr] = pw1.y;
        Ws[0][1][lk + 2][lr] = pw1.z; Ws[0][1][lk + 3][lr] = pw1.w;
        Ws[0][2][lk + 0][lr] = pw2.x; Ws[0][2][lk + 1][lr] = pw2.y;
        Ws[0][2][lk + 2][lr] = pw2.z; Ws[0][2][lk + 3][lr] = pw2.w;
    }
    __syncthreads();

    int buf = 0;
    for (int it = 0; it < WNIT; it++) {
        // issue global loads for next tile early (into registers)
        const int k0n = (it + 1) * WTK;
        if (it + 1 < WNIT) {
            if (tid < 128)
                pa = *(const float4*)&hprev[(size_t)(bm + lr) * Hh + k0n + lk];
            pw0 = *(const float4*)&whh[(size_t)(bn + lr) * Hh + k0n + lk];
            pw1 = *(const float4*)&whh[(size_t)(bn + Hh + lr) * Hh + k0n + lk];
            pw2 = *(const float4*)&whh[(size_t)(bn + 2 * Hh + lr) * Hh + k0n + lk];
        }
        // compute on current buffer
        #pragma unroll
        for (int kk = 0; kk < WTK; kk++) {
            float a0 = As[buf][kk][ty * 2 + 0];
            float a1 = As[buf][kk][ty * 2 + 1];
            float4 br = *(const float4*)&Ws[buf][0][kk][tx * 4];
            float4 bz = *(const float4*)&Ws[buf][1][kk][tx * 4];
            float4 bn4 = *(const float4*)&Ws[buf][2][kk][tx * 4];
            accr[0][0] = fmaf(a0, br.x, accr[0][0]);
            accr[0][1] = fmaf(a0, br.y, accr[0][1]);
            accr[0][2] = fmaf(a0, br.z, accr[0][2]);
            accr[0][3] = fmaf(a0, br.w, accr[0][3]);
            accr[1][0] = fmaf(a1, br.x, accr[1][0]);
            accr[1][1] = fmaf(a1, br.y, accr[1][1]);
            accr[1][2] = fmaf(a1, br.z, accr[1][2]);
            accr[1][3] = fmaf(a1, br.w, accr[1][3]);
            accz[0][0] = fmaf(a0, bz.x, accz[0][0]);
            accz[0][1] = fmaf(a0, bz.y, accz[0][1]);
            accz[0][2] = fmaf(a0, bz.z, accz[0][2]);
            accz[0][3] = fmaf(a0, bz.w, accz[0][3]);
            accz[1][0] = fmaf(a1, bz.x, accz[1][0]);
            accz[1][1] = fmaf(a1, bz.y, accz[1][1]);
            accz[1][2] = fmaf(a1, bz.z, accz[1][2]);
            accz[1][3] = fmaf(a1, bz.w, accz[1][3]);
            accn[0][0] = fmaf(a0, bn4.x, accn[0][0]);
            accn[0][1] = fmaf(a0, bn4.y, accn[0][1]);
            accn[0][2] = fmaf(a0, bn4.z, accn[0][2]);
            accn[0][3] = fmaf(a0, bn4.w, accn[0][3]);
            accn[1][0] = fmaf(a1, bn4.x, accn[1][0]);
            accn[1][1] = fmaf(a1, bn4.y, accn[1][1]);
            accn[1][2] = fmaf(a1, bn4.z, accn[1][2]);
            accn[1][3] = fmaf(a1, bn4.w, accn[1][3]);
        }
        __syncthreads();
        // store prefetched tile to other buffer
        if (it + 1 < WNIT) {
            int nb = buf ^ 1;
            if (tid < 128) {
                As[nb][lk + 0][lr] = pa.x; As[nb][lk + 1][lr] = pa.y;
                As[nb][lk + 2][lr] = pa.z; As[nb][lk + 3][lr] = pa.w;
            }
            Ws[nb][0][lk + 0][lr] = pw0.x; Ws[nb][0][lk + 1][lr] = pw0.y;
            Ws[nb][0][lk + 2][lr] = pw0.z; Ws[nb][0][lk + 3][lr] = pw0.w;
            Ws[nb][1][lk + 0][lr] = pw1.x; Ws[nb][1][lk + 1][lr] = pw1.y;
            Ws[nb][1][lk + 2][lr] = pw1.z; Ws[nb][1][lk + 3][lr] = pw1.w;
            Ws[nb][2][lk + 0][lr] = pw2.x; Ws[nb][2][lk + 1][lr] = pw2.y;
            Ws[nb][2][lk + 2][lr] = pw2.z; Ws[nb][2][lk + 3][lr] = pw2.w;
            __syncthreads();
            buf = nb;
        }
    }

    // ---- epilogue: GRU nonlinearity + table gather, write h_next ----
    const int c0 = bn + tx * 4;
    const float4 bhr = *(const float4*)&bhh[c0];
    const float4 bhz = *(const float4*)&bhh[c0 + Hh];
    const float4 bhn = *(const float4*)&bhh[c0 + 2 * Hh];
    #pragma unroll
    for (int i = 0; i < 2; i++) {
        const int gm = bm + ty * 2 + i;
        const int tok = __ldg(&tokens[gm * Ww + t]);
        const float* gi = g_table + (size_t)tok * G3;
        const float4 gir = *(const float4*)&gi[c0];
        const float4 giz = *(const float4*)&gi[c0 + Hh];
        const float4 gin = *(const float4*)&gi[c0 + 2 * Hh];
        const float4 hp = *(const float4*)&hprev[(size_t)gm * Hh + c0];
        float4 hn;
        {
            float r = sigmoidf(gir.x + accr[i][0] + bhr.x);
            float z = sigmoidf(giz.x + accz[i][0] + bhz.x);
            float n = tanhf(gin.x + r * (accn[i][0] + bhn.x));
            hn.x = (1.0f - z) * n + z * hp.x;
            r = sigmoidf(gir.y + accr[i][1] + bhr.y);
            z = sigmoidf(giz.y + accz[i][1] + bhz.y);
            n = tanhf(gin.y + r * (accn[i][1] + bhn.y));
            hn.y = (1.0f - z) * n + z * hp.y;
            r = sigmoidf(gir.z + accr[i][2] + bhr.z);
            z = sigmoidf(giz.z + accz[i][2] + bhz.z);
            n = tanhf(gin.z + r * (accn[i][2] + bhn.z));
            hn.z = (1.0f - z) * n + z * hp.z;
            r = sigmoidf(gir.w + accr[i][3] + bhr.w);
            z = sigmoidf(giz.w + accz[i][3] + bhz.w);
            n = tanhf(gin.w + r * (accn[i][3] + bhn.w));
            hn.w = (1.0f - z) * n + z * hp.w;
        }
        *(float4*)&hnext[(size_t)gm * Hh + c0] = hn;
        if (t == __ldg(&wlen[gm]) - 1)
            *(float4*)&utt_in[(size_t)gm * Hh + c0] = hn;
    }
}

// -------------------- init kernels --------------------
__global__ void zero_f(float* p, int n) {
    int i = blockIdx.x * blockDim.x + threadIdx.x;
    if (i < n) p[i] = 0.0f;
}
__global__ void bcast_h0(const float* __restrict__ h0, float* __restrict__ h) {
    int i = blockIdx.x * blockDim.x + threadIdx.x; // Bb*Hh
    h[i] = h0[i & (Hh - 1)];
}

// -------------------- small (batch=16) GRU step: warp per hidden column -------
__global__ void small_step(const float* __restrict__ gi, const float* __restrict__ whh,
                           const float* __restrict__ bhh, const float* __restrict__ hprev,
                           float* __restrict__ hnew, float* __restrict__ ys, int u) {
    int w = (blockIdx.x * blockDim.x + threadIdx.x) >> 5; // global warp id: Bb*Hh warps
    int lane = threadIdx.x & 31;
    int b = w >> 9;
    int c = w & (Hh - 1);
    const float* h  = hprev + b * Hh;
    const float* w0 = whh + (size_t)c * Hh;
    const float* w1 = whh + (size_t)(c + Hh) * Hh;
    const float* w2 = whh + (size_t)(c + 2*Hh) * Hh;
    float s0 = 0.f, s1 = 0.f, s2 = 0.f;
    #pragma unroll 4
    for (int k = lane; k < Hh; k += 32) {
        float hv = h[k];
        s0 = fmaf(hv, w0[k], s0);
        s1 = fmaf(hv, w1[k], s1);
        s2 = fmaf(hv, w2[k], s2);
    }
    #pragma unroll
    for (int o = 16; o; o >>= 1) {
        s0 += __shfl_down_sync(0xffffffffu, s0, o);
        s1 += __shfl_down_sync(0xffffffffu, s1, o);
        s2 += __shfl_down_sync(0xffffffffu, s2, o);
    }
    if (lane == 0) {
        const float* gir = gi + (size_t)(b * Uu + u) * G3;
        float r = sigmoidf(gir[c]        + s0 + bhh[c]);
        float z = sigmoidf(gir[c + Hh]   + s1 + bhh[c + Hh]);
        float n = tanhf   (gir[c + 2*Hh] + r * (s2 + bhh[c + 2*Hh]));
        float hn = (1.0f - z) * n + z * h[c];
        hnew[b * Hh + c] = hn;
        if (ys) ys[(size_t)(b * Uu + u) * Hh + c] = hn;
    }
}

// -------------------- adaptive gate: sigmoid(h_new @ w_g + b_g) > 0.5 --------
__global__ void utt_gate(const float* __restrict__ hnew, const float* __restrict__ wg,
                         const float* __restrict__ bg, const float* __restrict__ h0,
                         float* __restrict__ hnext, int u) {
    int b = blockIdx.x;      // 16 blocks
    int c = threadIdx.x;     // 512 threads
    __shared__ float red[Hh];
    __shared__ int sb;
    float hn = hnew[b * Hh + c];
    red[c] = hn * wg[c];
    __syncthreads();
    #pragma unroll
    for (int s = Hh / 2; s > 0; s >>= 1) {
        if (c < s) red[c] += red[c + s];
        __syncthreads();
    }
    if (c == 0) {
        float g = sigmoidf(red[0] + bg[0]);
        sb = (g > 0.5f) ? 1 : 0;
        g_bnd[b * Uu + u] = sb;
    }
    __syncthreads();
    hnext[b * Hh + c] = sb ? h0[c] : hn;
}

// -------------------- mask / compaction scatter ----------------------
__global__ void mask_scatter(const int* __restrict__ ulen) {
    int b = blockIdx.x;   // 16 blocks
    int c = threadIdx.x;  // 512 threads
    for (int u = 0; u < Uu; u++)
        g_seg_in[(size_t)(b * Uu + u) * Hh + c] = 0.0f;
    int ul = ulen[b];
    int cnt = 0;
    for (int u = 0; u < Uu; u++) {
        bool m = (u < ul) && (g_bnd[b * Uu + u] || (u == ul - 1));
        if (m) {
            g_seg_in[(size_t)(b * Uu + cnt) * Hh + c] =
                g_utt_ys[(size_t)(b * Uu + u) * Hh + c];
            cnt++;
        }
    }
    if (c == 0) g_slen[b] = cnt;
}

__global__ void write_slen(float* out, int out_size) {
    int b = threadIdx.x; // 16 threads
    if (b < Bb && SOUT + b < out_size) out[SOUT + b] = (float)g_slen[b];
}

// -------------------- host-side orchestration --------------------
extern "C" void kernel_launch(void* const* d_in, const int* in_sizes, int n_in,
                              void* d_out, int out_size) {
    const int*   input  = (const int*)  d_in[0];
    const int*   u_len  = (const int*)  d_in[1];
    const int*   w_len  = (const int*)  d_in[2];
    const float* emb    = (const float*)d_in[3];
    const float* w_ih_w = (const float*)d_in[4];
    const float* w_hh_w = (const float*)d_in[5];
    const float* b_ih_w = (const float*)d_in[6];
    const float* b_hh_w = (const float*)d_in[7];
    const float* w_ih_u = (const float*)d_in[8];
    const float* w_hh_u = (const float*)d_in[9];
    const float* b_ih_u = (const float*)d_in[10];
    const float* b_hh_u = (const float*)d_in[11];
    const float* w_g    = (const float*)d_in[12];
    const float* b_g    = (const float*)d_in[13];
    const float* w_ih_s = (const float*)d_in[14];
    const float* w_hh_s = (const float*)d_in[15];
    const float* b_ih_s = (const float*)d_in[16];
    const float* b_hh_s = (const float*)d_in[17];
    const float* h0     = (const float*)d_in[18];
    float* out = (float*)d_out;

    // Resolve device-symbol addresses fresh every call (no static caching).
    void* tmp;
    float *p_table, *p_wh0, *p_wh1, *p_utt_in, *p_gi_u;
    float *p_utt_h0, *p_utt_h1, *p_utt_hnew, *p_utt_ys, *p_gi_s;
    float *p_seg_in, *p_seg_h0, *p_seg_h1;
    cudaGetSymbolAddress(&tmp, g_table);   p_table = (float*)tmp;
    cudaGetSymbolAddress(&tmp, g_wh);      p_wh0 = (float*)tmp; p_wh1 = p_wh0 + BU*Hh;
    cudaGetSymbolAddress(&tmp, g_utt_in);  p_utt_in = (float*)tmp;
    cudaGetSymbolAddress(&tmp, g_gi_u);    p_gi_u = (float*)tmp;
    cudaGetSymbolAddress(&tmp, g_utt_h);   p_utt_h0 = (float*)tmp; p_utt_h1 = p_utt_h0 + Bb*Hh;
    cudaGetSymbolAddress(&tmp, g_utt_hnew);p_utt_hnew = (float*)tmp;
    cudaGetSymbolAddress(&tmp, g_utt_ys);  p_utt_ys = (float*)tmp;
    cudaGetSymbolAddress(&tmp, g_gi_s);    p_gi_s = (float*)tmp;
    cudaGetSymbolAddress(&tmp, g_seg_in);  p_seg_in = (float*)tmp;
    cudaGetSymbolAddress(&tmp, g_seg_h);   p_seg_h0 = (float*)tmp; p_seg_h1 = p_seg_h0 + Bb*Hh;

    // 1) Vocab-projected input table: table = emb @ w_ih_w^T + b_ih_w  (30000x1536, K=256)
    {
        dim3 grid((Vv + TM - 1) / TM, G3 / TN);
        gemm_nt<<<grid, 256>>>(emb, w_ih_w, b_ih_w, p_table, Vv, G3, Dd);
    }

    // 2) Word-level GRU: 96 sequential fused steps over 768 sequences
    zero_f<<<(BU * Hh + 255) / 256, 256>>>(p_wh0, BU * Hh);
    {
        float* hp[2] = {p_wh0, p_wh1};
        int cur = 0;
        dim3 wgrid(BU / WTM, Hh / WTN);   // (24, 8)
        for (int t = 0; t < Ww; t++) {
            word_step<<<wgrid, 256>>>(hp[cur], w_hh_w, b_hh_w, input, w_len,
                                      hp[1 - cur], p_utt_in, t);
            cur ^= 1;
        }
    }

    // 3) Utterance-level adaptive GRU
    {
        dim3 ggrid((BU + TM - 1) / TM, G3 / TN);
        gemm_nt<<<ggrid, 256>>>(p_utt_in, w_ih_u, b_ih_u, p_gi_u, BU, G3, Hh);
    }
    bcast_h0<<<(Bb * Hh + 255) / 256, 256>>>(h0, p_utt_h0);
    {
        float* hp[2] = {p_utt_h0, p_utt_h1};
        int cur = 0;
        int blocks = Bb * Hh * 32 / 256;     // 1024 blocks of 8 warps
        for (int u = 0; u < Uu; u++) {
            small_step<<<blocks, 256>>>(p_gi_u, w_hh_u, b_hh_u, hp[cur],
                                        p_utt_hnew, p_utt_ys, u);
            utt_gate<<<Bb, Hh>>>(p_utt_hnew, w_g, b_g, h0, hp[1 - cur], u);
            cur ^= 1;
        }
    }

    // 4) Boundary mask + compaction into segment inputs
    mask_scatter<<<Bb, Hh>>>(u_len);

    // 5) Segment-level GRU -> writes s_output directly into d_out
    {
        dim3 ggrid((BU + TM - 1) / TM, G3 / TN);
        gemm_nt<<<ggrid, 256>>>(p_seg_in, w_ih_s, b_ih_s, p_gi_s, BU, G3, Hh);
    }
    zero_f<<<(Bb * Hh + 255) / 256, 256>>>(p_seg_h0, Bb * Hh);
    {
        float* hp[2] = {p_seg_h0, p_seg_h1};
        int cur = 0;
        int blocks = Bb * Hh * 32 / 256;
        for (int u = 0; u < Uu; u++) {
            small_step<<<blocks, 256>>>(p_gi_s, w_hh_s, b_hh_s, hp[cur],
                                        hp[1 - cur], out, u);
            cur ^= 1;
        }
    }

    // 6) s_len tail (as float), guarded by out_size
    write_slen<<<1, 32>>>(out, out_size);
}